// round 8
// baseline (speedup 1.0000x reference)
#include <cuda_runtime.h>
#include <cuda_bf16.h>
#include <cstdint>
#include <cstddef>

// Problem constants
#define NB    8
#define CT    1024
#define LL    1024
#define HEADS 16
#define BN_EPS 1e-5f

// ---------------------------------------------------------------------------
// Scratch (static device allocations). Referenced ONLY from device code.
// ---------------------------------------------------------------------------
__device__ __nv_bfloat16 g_kT[(size_t)NB * HEADS * LL * 32];  // 8 MB  [n][h][l][32d]
__device__ __nv_bfloat16 g_qT[(size_t)NB * HEADS * LL * 32];  // 8 MB  [n][h][l][32d]
__device__ __nv_bfloat16 g_vB[(size_t)NB * CT * LL];          // 16 MB [n][c][l] == per-head [d][k]
__device__ float         g_mid[(size_t)NB * CT * LL];         // 32 MB tokens + kqv

// conv output modes
#define OUT_F32 0
#define OUT_KT  1
#define OUT_QT  2
#define OUT_VB  3

// ---------------------------------------------------------------------------
// mma.sync / ldmatrix / cp.async helpers (base PTX, sm_80+)
// ---------------------------------------------------------------------------
__device__ __forceinline__ uint32_t smem_u32(const void* p) {
    uint32_t a;
    asm("{ .reg .u64 t; cvta.to.shared.u64 t, %1; cvt.u32.u64 %0, t; }"
        : "=r"(a) : "l"(p));
    return a;
}

#define LDSM_X4(R, A)                                                        \
    asm volatile("ldmatrix.sync.aligned.m8n8.x4.shared.b16 {%0,%1,%2,%3}, [%4];" \
                 : "=r"((R)[0]), "=r"((R)[1]), "=r"((R)[2]), "=r"((R)[3])    \
                 : "r"(A))

#define MMA16816(C, A, B0, B1)                                               \
    asm volatile("mma.sync.aligned.m16n8k16.row.col.f32.bf16.bf16.f32 "      \
                 "{%0,%1,%2,%3}, {%4,%5,%6,%7}, {%8,%9}, {%0,%1,%2,%3};"     \
                 : "+f"((C)[0]), "+f"((C)[1]), "+f"((C)[2]), "+f"((C)[3])    \
                 : "r"((A)[0]), "r"((A)[1]), "r"((A)[2]), "r"((A)[3]),       \
                   "r"(B0), "r"(B1))

#define MMA_TF32(C, A, B0, B1)                                               \
    asm volatile("mma.sync.aligned.m16n8k8.row.col.f32.tf32.tf32.f32 "       \
                 "{%0,%1,%2,%3}, {%4,%5,%6,%7}, {%8,%9}, {%0,%1,%2,%3};"     \
                 : "+f"((C)[0]), "+f"((C)[1]), "+f"((C)[2]), "+f"((C)[3])    \
                 : "r"((A)[0]), "r"((A)[1]), "r"((A)[2]), "r"((A)[3]),       \
                   "r"(B0), "r"(B1))

#define CP_ASYNC16(smem, gptr)                                               \
    asm volatile("cp.async.cg.shared.global [%0], [%1], 16;"                 \
                 :: "r"(smem), "l"(gptr))
#define CP_COMMIT() asm volatile("cp.async.commit_group;" ::: "memory")
#define CP_WAIT(N)  asm volatile("cp.async.wait_group %0;" :: "n"(N) : "memory")

__device__ __forceinline__ uint32_t packbf2(float x, float y) {
    __nv_bfloat162 t = __floats2bfloat162_rn(x, y);
    return *(uint32_t*)&t;
}
__device__ __forceinline__ uint32_t f2tf(uint32_t bits) {
    uint32_t r;
    asm("cvt.rna.tf32.f32 %0, %1;" : "=r"(r) : "r"(bits));
    return r;
}
__device__ __forceinline__ float ex2f(float x) {
    float r;
    asm("ex2.approx.ftz.f32 %0, %1;" : "=f"(r) : "f"(x));
    return r;
}

// ---------------------------------------------------------------------------
// Grouped 1x1 conv + BN via tf32 mma.sync with cp.async double buffering.
// (unchanged from R7 — measured good)
// ---------------------------------------------------------------------------
template <int CO_TILE>
__global__ __launch_bounds__(256) void conv_mma_kernel(
    const float* __restrict__ x_ext, const float* __restrict__ w,
    const float* __restrict__ bias, const float* __restrict__ gamma,
    const float* __restrict__ beta, const float* __restrict__ mean,
    const float* __restrict__ var,
    float* out_ext, int use_mid_src, int mode, int use_residual,
    int cin_per_g, int cout_per_g, int cout_total)
{
    constexpr int MT = CO_TILE / 32;
    constexpr int WSZ = CO_TILE * 36;
    constexpr int XSZ = 32 * 136;
    extern __shared__ uint32_t dynsm[];
    uint32_t* Wsm = dynsm;
    uint32_t* Xsm = dynsm + 2 * WSZ;
    const uint32_t ws_addr = smem_u32(Wsm);
    const uint32_t xs_addr = smem_u32(Xsm);

    const float* x = use_mid_src ? g_mid : x_ext;

    const int n   = blockIdx.z;
    const int co0 = blockIdx.y * CO_TILE;
    const int l0  = blockIdx.x * 128;
    const int g   = co0 / cout_per_g;

    const float* xg = x + ((size_t)n * CT + (size_t)g * cin_per_g) * LL + l0;

    const int tid  = threadIdx.x;
    const int wrp  = tid >> 5;
    const int lane = tid & 31;
    const int grp  = lane >> 2;
    const int tg   = lane & 3;
    const int wm   = wrp >> 2;
    const int wn   = wrp & 3;

    float c[MT][4][4];
#pragma unroll
    for (int mt = 0; mt < MT; mt++)
#pragma unroll
        for (int nt = 0; nt < 4; nt++)
#pragma unroll
            for (int j = 0; j < 4; j++) c[mt][nt][j] = 0.f;

    const int nchunks = cin_per_g >> 5;

    auto issue = [&](int ch, int buf) {
#pragma unroll
        for (int i = 0; i < 4; i++) {
            int idx = tid + i * 256;
            int r = idx >> 5, c4 = idx & 31;
            uint32_t dst = xs_addr + (uint32_t)(buf * XSZ + r * 136 + c4 * 4) * 4;
            CP_ASYNC16(dst, xg + (size_t)(ch * 32 + r) * LL + c4 * 4);
        }
#pragma unroll
        for (int i = 0; i < CO_TILE / 32; i++) {
            int idx = tid + i * 256;
            int r = idx >> 3, k4 = idx & 7;
            uint32_t dst = ws_addr + (uint32_t)(buf * WSZ + r * 36 + k4 * 4) * 4;
            CP_ASYNC16(dst, w + (size_t)(co0 + r) * cin_per_g + ch * 32 + k4 * 4);
        }
        CP_COMMIT();
    };

    issue(0, 0);
    for (int ch = 0; ch < nchunks; ch++) {
        if (ch + 1 < nchunks) {
            issue(ch + 1, (ch + 1) & 1);
            CP_WAIT(1);
        } else {
            CP_WAIT(0);
        }
        __syncthreads();

        const uint32_t* Wb = Wsm + (ch & 1) * WSZ;
        const uint32_t* Xb = Xsm + (ch & 1) * XSZ;

#pragma unroll
        for (int ks = 0; ks < 4; ks++) {
            uint32_t a[MT][4], b[4][2];
#pragma unroll
            for (int mt = 0; mt < MT; mt++) {
                int r0 = (wm * (CO_TILE / 2) + mt * 16 + grp) * 36 + ks * 8 + tg;
                a[mt][0] = f2tf(Wb[r0]);
                a[mt][1] = f2tf(Wb[r0 + 8 * 36]);
                a[mt][2] = f2tf(Wb[r0 + 4]);
                a[mt][3] = f2tf(Wb[r0 + 8 * 36 + 4]);
            }
#pragma unroll
            for (int nt = 0; nt < 4; nt++) {
                int xb = (ks * 8 + tg) * 136 + wn * 32 + nt * 8 + grp;
                b[nt][0] = f2tf(Xb[xb]);
                b[nt][1] = f2tf(Xb[xb + 4 * 136]);
            }
#pragma unroll
            for (int mt = 0; mt < MT; mt++)
#pragma unroll
                for (int nt = 0; nt < 4; nt++)
                    MMA_TF32(c[mt][nt], a[mt], b[nt][0], b[nt][1]);
        }
        __syncthreads();
    }

#pragma unroll
    for (int mt = 0; mt < MT; mt++) {
        int coA = co0 + wm * (CO_TILE / 2) + mt * 16 + grp;
        int coB = coA + 8;
        float invA = gamma[coA] * rsqrtf(var[coA] + BN_EPS);
        float shA  = bias[coA] * invA + beta[coA] - mean[coA] * invA;
        float invB = gamma[coB] * rsqrtf(var[coB] + BN_EPS);
        float shB  = bias[coB] * invB + beta[coB] - mean[coB] * invB;

#pragma unroll
        for (int nt = 0; nt < 4; nt++) {
            int col = l0 + wn * 32 + nt * 8 + tg * 2;
            float vA0 = c[mt][nt][0] * invA + shA;
            float vA1 = c[mt][nt][1] * invA + shA;
            float vB0 = c[mt][nt][2] * invB + shB;
            float vB1 = c[mt][nt][3] * invB + shB;

            if (mode == OUT_F32) {
                size_t iA = ((size_t)n * cout_total + coA) * LL + col;
                size_t iB = ((size_t)n * cout_total + coB) * LL + col;
                if (use_residual) {
                    vA0 += x[iA]; vA1 += x[iA + 1];
                    vB0 += x[iB]; vB1 += x[iB + 1];
                }
                *(float2*)&out_ext[iA] = make_float2(vA0, vA1);
                *(float2*)&out_ext[iB] = make_float2(vB0, vB1);
            } else if (mode == OUT_VB) {
                size_t iA = ((size_t)n * cout_total + coA) * LL + col;
                size_t iB = ((size_t)n * cout_total + coB) * LL + col;
                *(uint32_t*)&g_vB[iA] = packbf2(vA0, vA1);
                *(uint32_t*)&g_vB[iB] = packbf2(vB0, vB1);
            } else {
                __nv_bfloat16* dst = (mode == OUT_KT) ? g_kT : g_qT;
                int hA = coA >> 5, dA = coA & 31;
                int hB = coB >> 5, dB = coB & 31;
                size_t bA = (((size_t)n * HEADS + hA) * LL + col) * 32 + dA;
                size_t bB = (((size_t)n * HEADS + hB) * LL + col) * 32 + dB;
                dst[bA]      = __float2bfloat16(vA0);
                dst[bA + 32] = __float2bfloat16(vA1);
                dst[bB]      = __float2bfloat16(vB0);
                dst[bB + 32] = __float2bfloat16(vB1);
            }
        }
    }
}

// ---------------------------------------------------------------------------
// Attention v2: 128 threads (4 warps), warp owns 32 q rows (2 m-tiles).
// cp.async double-buffered K/V tiles; interleaved S->exp->PV per 16-k strip;
// ex2.approx for exp. Dyn smem: Q 10 KB + 2x K 10 KB + 2x V 17 KB = 65.5 KB.
// ---------------------------------------------------------------------------
#define ASMQ   0
#define ASMK   10240
#define ASMK_SZ 10240
#define ASMV   (ASMK + 2 * ASMK_SZ)
#define ASMV_SZ 17408
#define SM_ATT_TOTAL (ASMV + 2 * ASMV_SZ)   // 65536 B

__global__ __launch_bounds__(128, 3) void attn_mma_kernel(
    const float* __restrict__ tokens)
{
    extern __shared__ char att_sm[];
    const uint32_t sb = smem_u32(att_sm);

    const int tid  = threadIdx.x;
    const int w    = tid >> 5;
    const int lane = tid & 31;
    const int grp  = lane >> 2;
    const int tg   = lane & 3;
    const int q0   = blockIdx.x * 128;
    const int h    = blockIdx.y;
    const int n    = blockIdx.z;

    const int rowoff = (lane & 7) + ((lane >> 4) & 1) * 8;
    const int colsel = (lane >> 3) & 1;

    // Q tile [128 q][32 d] -> smem stride 80 B (1 thread/row)
    {
        const uint4* src = (const uint4*)(g_qT +
            (((size_t)n * HEADS + h) * LL + q0 + tid) * 32);
#pragma unroll
        for (int u = 0; u < 4; u++)
            *(uint4*)(att_sm + ASMQ + tid * 80 + u * 16) = src[u];
    }

    // K/V chunk producer (cp.async)
    auto issue = [&](int c, int buf) {
        const char* kg = (const char*)(g_kT +
            (((size_t)n * HEADS + h) * LL + c * 128 + tid) * 32);
#pragma unroll
        for (int u = 0; u < 4; u++)
            CP_ASYNC16(sb + ASMK + buf * ASMK_SZ + tid * 80 + u * 16, kg + u * 16);
        const char* vg = (const char*)(g_vB +
            ((size_t)n * CT + h * 64 + (tid >> 1)) * LL + c * 128 + (tid & 1) * 64);
        uint32_t vdst = sb + ASMV + buf * ASMV_SZ + (tid >> 1) * 272 + (tid & 1) * 128;
#pragma unroll
        for (int u = 0; u < 8; u++)
            CP_ASYNC16(vdst + u * 16, vg + u * 16);
        CP_COMMIT();
    };

    issue(0, 0);
    __syncthreads();   // Q visible

    // Q fragments (chunk-invariant): qa[mtile][kstep][4]
    uint32_t qa[2][2][4];
    {
        int r = lane & 15, cb = (lane >> 4) * 16;
#pragma unroll
        for (int mt = 0; mt < 2; mt++)
#pragma unroll
            for (int ks = 0; ks < 2; ks++) {
                uint32_t addr = sb + ASMQ
                    + (uint32_t)((w * 32 + mt * 16 + r) * 80 + ks * 32 + cb);
                LDSM_X4(qa[mt][ks], addr);
            }
    }

    const float SC2 = 1.4426950408889634f / 32.0f;  // log2(e)/sqrt(L)
    float o[2][8][4];
#pragma unroll
    for (int mt = 0; mt < 2; mt++)
#pragma unroll
        for (int i = 0; i < 8; i++)
#pragma unroll
            for (int j = 0; j < 4; j++) o[mt][i][j] = 0.f;
    float rs[2][2] = {{0.f, 0.f}, {0.f, 0.f}};

    for (int c = 0; c < 8; c++) {
        if (c + 1 < 8) {
            issue(c + 1, (c + 1) & 1);
            CP_WAIT(1);
        } else {
            CP_WAIT(0);
        }
        __syncthreads();

        const uint32_t kb = sb + ASMK + (c & 1) * ASMK_SZ;
        const uint32_t vb = sb + ASMV + (c & 1) * ASMV_SZ;

#pragma unroll
        for (int np = 0; np < 8; np++) {   // 16-k strip
            float s[2][2][4];
#pragma unroll
            for (int mt = 0; mt < 2; mt++)
#pragma unroll
                for (int nt = 0; nt < 2; nt++)
#pragma unroll
                    for (int j = 0; j < 4; j++) s[mt][nt][j] = 0.f;

#pragma unroll
            for (int ks = 0; ks < 2; ks++) {
                uint32_t b[4];
                LDSM_X4(b, kb + (uint32_t)((np * 16 + rowoff) * 80
                                           + ks * 32 + colsel * 16));
#pragma unroll
                for (int mt = 0; mt < 2; mt++) {
                    MMA16816(s[mt][0], qa[mt][ks], b[0], b[1]);
                    MMA16816(s[mt][1], qa[mt][ks], b[2], b[3]);
                }
            }

            uint32_t a[2][4];
#pragma unroll
            for (int mt = 0; mt < 2; mt++) {
                float e0a = ex2f(s[mt][0][0] * SC2);
                float e0b = ex2f(s[mt][0][1] * SC2);
                float e0c = ex2f(s[mt][0][2] * SC2);
                float e0d = ex2f(s[mt][0][3] * SC2);
                float e1a = ex2f(s[mt][1][0] * SC2);
                float e1b = ex2f(s[mt][1][1] * SC2);
                float e1c = ex2f(s[mt][1][2] * SC2);
                float e1d = ex2f(s[mt][1][3] * SC2);
                rs[mt][0] += e0a + e0b + e1a + e1b;
                rs[mt][1] += e0c + e0d + e1c + e1d;
                a[mt][0] = packbf2(e0a, e0b);
                a[mt][1] = packbf2(e0c, e0d);
                a[mt][2] = packbf2(e1a, e1b);
                a[mt][3] = packbf2(e1c, e1d);
            }

#pragma unroll
            for (int dp = 0; dp < 4; dp++) {
                uint32_t bv[4];
                LDSM_X4(bv, vb + (uint32_t)((dp * 16 + rowoff) * 272
                                            + np * 32 + colsel * 16));
#pragma unroll
                for (int mt = 0; mt < 2; mt++) {
                    MMA16816(o[mt][2 * dp],     a[mt], bv[0], bv[1]);
                    MMA16816(o[mt][2 * dp + 1], a[mt], bv[2], bv[3]);
                }
            }
        }
        __syncthreads();   // readers done before next issue overwrites
    }

    // rowsum reduce within quad
#pragma unroll
    for (int mt = 0; mt < 2; mt++)
#pragma unroll
        for (int j = 0; j < 2; j++) {
            rs[mt][j] += __shfl_xor_sync(0xFFFFFFFF, rs[mt][j], 1);
            rs[mt][j] += __shfl_xor_sync(0xFFFFFFFF, rs[mt][j], 2);
        }

    // write: g_mid = tokens + O/lsum
#pragma unroll
    for (int mt = 0; mt < 2; mt++) {
        const int qg0 = q0 + w * 32 + mt * 16 + grp;
        const float inv0 = 1.0f / rs[mt][0];
        const float inv1 = 1.0f / rs[mt][1];
#pragma unroll
        for (int dt = 0; dt < 8; dt++) {
            int d = dt * 8 + tg * 2;
            size_t i00 = ((size_t)n * CT + h * 64 + d) * LL + qg0;
            size_t i01 = i00 + LL;
            g_mid[i00]     = tokens[i00]     + o[mt][dt][0] * inv0;
            g_mid[i01]     = tokens[i01]     + o[mt][dt][1] * inv0;
            g_mid[i00 + 8] = tokens[i00 + 8] + o[mt][dt][2] * inv1;
            g_mid[i01 + 8] = tokens[i01 + 8] + o[mt][dt][3] * inv1;
        }
    }
}

// ---------------------------------------------------------------------------
extern "C" void kernel_launch(void* const* d_in, const int* in_sizes, int n_in,
                              void* d_out, int out_size)
{
    (void)in_sizes; (void)n_in; (void)out_size;
    const float* tokens = (const float*)d_in[0];
    const float* kw = (const float*)d_in[1];
    const float* kb = (const float*)d_in[2];
    const float* kg = (const float*)d_in[3];
    const float* kbe = (const float*)d_in[4];
    const float* km = (const float*)d_in[5];
    const float* kvv = (const float*)d_in[6];
    const float* qw = (const float*)d_in[7];
    const float* qb = (const float*)d_in[8];
    const float* qg = (const float*)d_in[9];
    const float* qbe = (const float*)d_in[10];
    const float* qm = (const float*)d_in[11];
    const float* qvv = (const float*)d_in[12];
    const float* vw = (const float*)d_in[13];
    const float* vb = (const float*)d_in[14];
    const float* vg = (const float*)d_in[15];
    const float* vbe = (const float*)d_in[16];
    const float* vm = (const float*)d_in[17];
    const float* vvv = (const float*)d_in[18];
    const float* fw = (const float*)d_in[19];
    const float* fb = (const float*)d_in[20];
    const float* fg = (const float*)d_in[21];
    const float* fbe = (const float*)d_in[22];
    const float* fm = (const float*)d_in[23];
    const float* fvv = (const float*)d_in[24];

    const int smem64  = (2 * 64 * 36 + 2 * 32 * 136) * 4;    // 53248 B
    const int smem128 = (2 * 128 * 36 + 2 * 32 * 136) * 4;   // 71680 B
    cudaFuncSetAttribute(conv_mma_kernel<64>,
                         cudaFuncAttributeMaxDynamicSharedMemorySize, smem64);
    cudaFuncSetAttribute(conv_mma_kernel<128>,
                         cudaFuncAttributeMaxDynamicSharedMemorySize, smem128);
    cudaFuncSetAttribute(attn_mma_kernel,
                         cudaFuncAttributeMaxDynamicSharedMemorySize, SM_ATT_TOTAL);

    // K, Q convs: cout=512, groups=8 -> transposed bf16 [n][h][l][32]
    conv_mma_kernel<64><<<dim3(8, 8, 8), 256, smem64>>>(
        tokens, kw, kb, kg, kbe, km, kvv, nullptr, 0, OUT_KT, 0, 128, 64, 512);
    conv_mma_kernel<64><<<dim3(8, 8, 8), 256, smem64>>>(
        tokens, qw, qb, qg, qbe, qm, qvv, nullptr, 0, OUT_QT, 0, 128, 64, 512);
    // V conv: cout=1024, groups=8 -> bf16 [n][c][l]
    conv_mma_kernel<128><<<dim3(8, 8, 8), 256, smem128>>>(
        tokens, vw, vb, vg, vbe, vm, vvv, nullptr, 0, OUT_VB, 0, 128, 128, 1024);

    // Attention + residual -> g_mid
    attn_mma_kernel<<<dim3(8, HEADS, 8), 128, SM_ATT_TOTAL>>>(tokens);

    // FF conv (groups=1, tf32) + residual: g_mid -> d_out
    conv_mma_kernel<128><<<dim3(8, 8, 8), 256, smem128>>>(
        nullptr, fw, fb, fg, fbe, fm, fvv, (float*)d_out, 1, OUT_F32, 1,
        1024, 1024, 1024);
}

// round 9
// speedup vs baseline: 1.0460x; 1.0460x over previous
#include <cuda_runtime.h>
#include <cuda_bf16.h>
#include <cstdint>
#include <cstddef>

// Problem constants
#define NB    8
#define CT    1024
#define LL    1024
#define HEADS 16
#define BN_EPS 1e-5f

// ---------------------------------------------------------------------------
// Scratch (static device allocations). Referenced ONLY from device code.
// ---------------------------------------------------------------------------
__device__ __nv_bfloat16 g_kT[(size_t)NB * HEADS * LL * 32];  // 8 MB  [n][h][l][32d]
__device__ __nv_bfloat16 g_qT[(size_t)NB * HEADS * LL * 32];  // 8 MB  [n][h][l][32d]
__device__ __nv_bfloat16 g_vB[(size_t)NB * CT * LL];          // 16 MB [n][c][l] == per-head [d][k]
__device__ float         g_mid[(size_t)NB * CT * LL];         // 32 MB tokens + kqv

// conv output modes
#define OUT_F32 0
#define OUT_KT  1
#define OUT_QT  2
#define OUT_VB  3

// ---------------------------------------------------------------------------
// mma.sync / ldmatrix / cp.async helpers (base PTX, sm_80+)
// ---------------------------------------------------------------------------
__device__ __forceinline__ uint32_t smem_u32(const void* p) {
    uint32_t a;
    asm("{ .reg .u64 t; cvta.to.shared.u64 t, %1; cvt.u32.u64 %0, t; }"
        : "=r"(a) : "l"(p));
    return a;
}

#define LDSM_X4(R, A)                                                        \
    asm volatile("ldmatrix.sync.aligned.m8n8.x4.shared.b16 {%0,%1,%2,%3}, [%4];" \
                 : "=r"((R)[0]), "=r"((R)[1]), "=r"((R)[2]), "=r"((R)[3])    \
                 : "r"(A))

#define MMA16816(C, A, B0, B1)                                               \
    asm volatile("mma.sync.aligned.m16n8k16.row.col.f32.bf16.bf16.f32 "      \
                 "{%0,%1,%2,%3}, {%4,%5,%6,%7}, {%8,%9}, {%0,%1,%2,%3};"     \
                 : "+f"((C)[0]), "+f"((C)[1]), "+f"((C)[2]), "+f"((C)[3])    \
                 : "r"((A)[0]), "r"((A)[1]), "r"((A)[2]), "r"((A)[3]),       \
                   "r"(B0), "r"(B1))

#define MMA_TF32(C, A, B0, B1)                                               \
    asm volatile("mma.sync.aligned.m16n8k8.row.col.f32.tf32.tf32.f32 "       \
                 "{%0,%1,%2,%3}, {%4,%5,%6,%7}, {%8,%9}, {%0,%1,%2,%3};"     \
                 : "+f"((C)[0]), "+f"((C)[1]), "+f"((C)[2]), "+f"((C)[3])    \
                 : "r"((A)[0]), "r"((A)[1]), "r"((A)[2]), "r"((A)[3]),       \
                   "r"(B0), "r"(B1))

#define CP_ASYNC16(smem, gptr)                                               \
    asm volatile("cp.async.cg.shared.global [%0], [%1], 16;"                 \
                 :: "r"(smem), "l"(gptr))
#define CP_COMMIT() asm volatile("cp.async.commit_group;" ::: "memory")
#define CP_WAIT(N)  asm volatile("cp.async.wait_group %0;" :: "n"(N) : "memory")

__device__ __forceinline__ uint32_t packbf2(float x, float y) {
    __nv_bfloat162 t = __floats2bfloat162_rn(x, y);
    return *(uint32_t*)&t;
}
__device__ __forceinline__ uint32_t f2tf(uint32_t bits) {
    uint32_t r;
    asm("cvt.rna.tf32.f32 %0, %1;" : "=r"(r) : "r"(bits));
    return r;
}
__device__ __forceinline__ float ex2f(float x) {
    float r;
    asm("ex2.approx.ftz.f32 %0, %1;" : "=f"(r) : "f"(x));
    return r;
}

// ---------------------------------------------------------------------------
// Grouped 1x1 conv + BN via tf32 mma.sync with cp.async double buffering.
// (unchanged from R7 — measured good)
// ---------------------------------------------------------------------------
template <int CO_TILE>
__global__ __launch_bounds__(256) void conv_mma_kernel(
    const float* __restrict__ x_ext, const float* __restrict__ w,
    const float* __restrict__ bias, const float* __restrict__ gamma,
    const float* __restrict__ beta, const float* __restrict__ mean,
    const float* __restrict__ var,
    float* out_ext, int use_mid_src, int mode, int use_residual,
    int cin_per_g, int cout_per_g, int cout_total)
{
    constexpr int MT = CO_TILE / 32;
    constexpr int WSZ = CO_TILE * 36;
    constexpr int XSZ = 32 * 136;
    extern __shared__ uint32_t dynsm[];
    uint32_t* Wsm = dynsm;
    uint32_t* Xsm = dynsm + 2 * WSZ;
    const uint32_t ws_addr = smem_u32(Wsm);
    const uint32_t xs_addr = smem_u32(Xsm);

    const float* x = use_mid_src ? g_mid : x_ext;

    const int n   = blockIdx.z;
    const int co0 = blockIdx.y * CO_TILE;
    const int l0  = blockIdx.x * 128;
    const int g   = co0 / cout_per_g;

    const float* xg = x + ((size_t)n * CT + (size_t)g * cin_per_g) * LL + l0;

    const int tid  = threadIdx.x;
    const int wrp  = tid >> 5;
    const int lane = tid & 31;
    const int grp  = lane >> 2;
    const int tg   = lane & 3;
    const int wm   = wrp >> 2;
    const int wn   = wrp & 3;

    float c[MT][4][4];
#pragma unroll
    for (int mt = 0; mt < MT; mt++)
#pragma unroll
        for (int nt = 0; nt < 4; nt++)
#pragma unroll
            for (int j = 0; j < 4; j++) c[mt][nt][j] = 0.f;

    const int nchunks = cin_per_g >> 5;

    auto issue = [&](int ch, int buf) {
#pragma unroll
        for (int i = 0; i < 4; i++) {
            int idx = tid + i * 256;
            int r = idx >> 5, c4 = idx & 31;
            uint32_t dst = xs_addr + (uint32_t)(buf * XSZ + r * 136 + c4 * 4) * 4;
            CP_ASYNC16(dst, xg + (size_t)(ch * 32 + r) * LL + c4 * 4);
        }
#pragma unroll
        for (int i = 0; i < CO_TILE / 32; i++) {
            int idx = tid + i * 256;
            int r = idx >> 3, k4 = idx & 7;
            uint32_t dst = ws_addr + (uint32_t)(buf * WSZ + r * 36 + k4 * 4) * 4;
            CP_ASYNC16(dst, w + (size_t)(co0 + r) * cin_per_g + ch * 32 + k4 * 4);
        }
        CP_COMMIT();
    };

    issue(0, 0);
    for (int ch = 0; ch < nchunks; ch++) {
        if (ch + 1 < nchunks) {
            issue(ch + 1, (ch + 1) & 1);
            CP_WAIT(1);
        } else {
            CP_WAIT(0);
        }
        __syncthreads();

        const uint32_t* Wb = Wsm + (ch & 1) * WSZ;
        const uint32_t* Xb = Xsm + (ch & 1) * XSZ;

#pragma unroll
        for (int ks = 0; ks < 4; ks++) {
            uint32_t a[MT][4], b[4][2];
#pragma unroll
            for (int mt = 0; mt < MT; mt++) {
                int r0 = (wm * (CO_TILE / 2) + mt * 16 + grp) * 36 + ks * 8 + tg;
                a[mt][0] = f2tf(Wb[r0]);
                a[mt][1] = f2tf(Wb[r0 + 8 * 36]);
                a[mt][2] = f2tf(Wb[r0 + 4]);
                a[mt][3] = f2tf(Wb[r0 + 8 * 36 + 4]);
            }
#pragma unroll
            for (int nt = 0; nt < 4; nt++) {
                int xb = (ks * 8 + tg) * 136 + wn * 32 + nt * 8 + grp;
                b[nt][0] = f2tf(Xb[xb]);
                b[nt][1] = f2tf(Xb[xb + 4 * 136]);
            }
#pragma unroll
            for (int mt = 0; mt < MT; mt++)
#pragma unroll
                for (int nt = 0; nt < 4; nt++)
                    MMA_TF32(c[mt][nt], a[mt], b[nt][0], b[nt][1]);
        }
        __syncthreads();
    }

#pragma unroll
    for (int mt = 0; mt < MT; mt++) {
        int coA = co0 + wm * (CO_TILE / 2) + mt * 16 + grp;
        int coB = coA + 8;
        float invA = gamma[coA] * rsqrtf(var[coA] + BN_EPS);
        float shA  = bias[coA] * invA + beta[coA] - mean[coA] * invA;
        float invB = gamma[coB] * rsqrtf(var[coB] + BN_EPS);
        float shB  = bias[coB] * invB + beta[coB] - mean[coB] * invB;

#pragma unroll
        for (int nt = 0; nt < 4; nt++) {
            int col = l0 + wn * 32 + nt * 8 + tg * 2;
            float vA0 = c[mt][nt][0] * invA + shA;
            float vA1 = c[mt][nt][1] * invA + shA;
            float vB0 = c[mt][nt][2] * invB + shB;
            float vB1 = c[mt][nt][3] * invB + shB;

            if (mode == OUT_F32) {
                size_t iA = ((size_t)n * cout_total + coA) * LL + col;
                size_t iB = ((size_t)n * cout_total + coB) * LL + col;
                if (use_residual) {
                    vA0 += x[iA]; vA1 += x[iA + 1];
                    vB0 += x[iB]; vB1 += x[iB + 1];
                }
                *(float2*)&out_ext[iA] = make_float2(vA0, vA1);
                *(float2*)&out_ext[iB] = make_float2(vB0, vB1);
            } else if (mode == OUT_VB) {
                size_t iA = ((size_t)n * cout_total + coA) * LL + col;
                size_t iB = ((size_t)n * cout_total + coB) * LL + col;
                *(uint32_t*)&g_vB[iA] = packbf2(vA0, vA1);
                *(uint32_t*)&g_vB[iB] = packbf2(vB0, vB1);
            } else {
                __nv_bfloat16* dst = (mode == OUT_KT) ? g_kT : g_qT;
                int hA = coA >> 5, dA = coA & 31;
                int hB = coB >> 5, dB = coB & 31;
                size_t bA = (((size_t)n * HEADS + hA) * LL + col) * 32 + dA;
                size_t bB = (((size_t)n * HEADS + hB) * LL + col) * 32 + dB;
                dst[bA]      = __float2bfloat16(vA0);
                dst[bA + 32] = __float2bfloat16(vA1);
                dst[bB]      = __float2bfloat16(vB0);
                dst[bB + 32] = __float2bfloat16(vB1);
            }
        }
    }
}

// ---------------------------------------------------------------------------
// Attention v3 = R5 tiling (8 warps x 16 q-rows, high TLP) + cp.async
// double-buffered K/V + ex2.approx. 256 threads.
// Dyn smem: Q 10 KB + 2x K 10 KB + 2x V 17 KB = 65536 B.
// ---------------------------------------------------------------------------
#define ASMQ    0
#define ASMK    10240
#define ASMK_SZ 10240
#define ASMV    (ASMK + 2 * ASMK_SZ)
#define ASMV_SZ 17408
#define SM_ATT_TOTAL (ASMV + 2 * ASMV_SZ)   // 65536 B

__global__ __launch_bounds__(256) void attn_mma_kernel(
    const float* __restrict__ tokens)
{
    extern __shared__ char att_sm[];
    const uint32_t sb = smem_u32(att_sm);

    const int tid  = threadIdx.x;
    const int w    = tid >> 5;
    const int lane = tid & 31;
    const int grp  = lane >> 2;
    const int tg   = lane & 3;
    const int q0   = blockIdx.x * 128;
    const int h    = blockIdx.y;
    const int n    = blockIdx.z;

    const int rowoff = (lane & 7) + ((lane >> 4) & 1) * 8;
    const int colsel = (lane >> 3) & 1;

    // Q tile [128 q][32 d] -> smem stride 80 B (2 thr/row, regular stores)
    {
        int row = tid >> 1, half = tid & 1;
        const uint4* src = (const uint4*)(g_qT +
            (((size_t)n * HEADS + h) * LL + q0 + row) * 32 + half * 16);
        uint4* dst = (uint4*)(att_sm + ASMQ + row * 80 + half * 32);
        dst[0] = src[0];
        dst[1] = src[1];
    }

    // K/V chunk producer (cp.async). K: 2 thr/row (32 B each); V: 4 thr/row.
    auto issue = [&](int c, int buf) {
        {
            int row = tid >> 1, half = tid & 1;
            const char* kg = (const char*)(g_kT +
                (((size_t)n * HEADS + h) * LL + c * 128 + row) * 32 + half * 16);
            uint32_t kdst = sb + ASMK + buf * ASMK_SZ + row * 80 + half * 32;
            CP_ASYNC16(kdst, kg);
            CP_ASYNC16(kdst + 16, kg + 16);
        }
        {
            int row = tid >> 2, quar = tid & 3;
            const char* vg = (const char*)(g_vB +
                ((size_t)n * CT + h * 64 + row) * LL + c * 128 + quar * 32);
            uint32_t vdst = sb + ASMV + buf * ASMV_SZ + row * 272 + quar * 64;
#pragma unroll
            for (int u = 0; u < 4; u++)
                CP_ASYNC16(vdst + u * 16, vg + u * 16);
        }
        CP_COMMIT();
    };

    issue(0, 0);
    __syncthreads();   // Q visible

    // Q fragments (chunk-invariant)
    uint32_t qa[2][4];
    {
        int r = lane & 15, cb = (lane >> 4) * 16;
#pragma unroll
        for (int ks = 0; ks < 2; ks++) {
            uint32_t addr = sb + ASMQ + (uint32_t)((w * 16 + r) * 80 + ks * 32 + cb);
            LDSM_X4(qa[ks], addr);
        }
    }

    const float SC2 = 1.4426950408889634f / 32.0f;   // log2(e)/sqrt(L)
    float o[8][4];
#pragma unroll
    for (int i = 0; i < 8; i++)
#pragma unroll
        for (int j = 0; j < 4; j++) o[i][j] = 0.f;
    float rs0 = 0.f, rs1 = 0.f;

    for (int c = 0; c < 8; c++) {
        if (c + 1 < 8) {
            issue(c + 1, (c + 1) & 1);
            CP_WAIT(1);
        } else {
            CP_WAIT(0);
        }
        __syncthreads();

        const uint32_t kb = sb + ASMK + (c & 1) * ASMK_SZ;
        const uint32_t vb = sb + ASMV + (c & 1) * ASMV_SZ;

        // GEMM1: S fragments s[16 ntiles][4]
        float s[16][4];
#pragma unroll
        for (int i = 0; i < 16; i++)
#pragma unroll
            for (int j = 0; j < 4; j++) s[i][j] = 0.f;

#pragma unroll
        for (int np = 0; np < 8; np++) {
#pragma unroll
            for (int ks = 0; ks < 2; ks++) {
                uint32_t b[4];
                LDSM_X4(b, kb + (uint32_t)((np * 16 + rowoff) * 80
                                           + ks * 32 + colsel * 16));
                MMA16816(s[2 * np],     qa[ks], b[0], b[1]);
                MMA16816(s[2 * np + 1], qa[ks], b[2], b[3]);
            }
        }

        // exp (MUFU) + repack to A fragments, then GEMM2 into O
#pragma unroll
        for (int kk = 0; kk < 8; kk++) {
            float e0a = ex2f(s[2 * kk][0] * SC2);
            float e0b = ex2f(s[2 * kk][1] * SC2);
            float e0c = ex2f(s[2 * kk][2] * SC2);
            float e0d = ex2f(s[2 * kk][3] * SC2);
            float e1a = ex2f(s[2 * kk + 1][0] * SC2);
            float e1b = ex2f(s[2 * kk + 1][1] * SC2);
            float e1c = ex2f(s[2 * kk + 1][2] * SC2);
            float e1d = ex2f(s[2 * kk + 1][3] * SC2);
            rs0 += e0a + e0b + e1a + e1b;
            rs1 += e0c + e0d + e1c + e1d;
            uint32_t a[4];
            a[0] = packbf2(e0a, e0b);
            a[1] = packbf2(e0c, e0d);
            a[2] = packbf2(e1a, e1b);
            a[3] = packbf2(e1c, e1d);

#pragma unroll
            for (int dp = 0; dp < 4; dp++) {
                uint32_t bv[4];
                LDSM_X4(bv, vb + (uint32_t)((dp * 16 + rowoff) * 272
                                            + kk * 32 + colsel * 16));
                MMA16816(o[2 * dp],     a, bv[0], bv[1]);
                MMA16816(o[2 * dp + 1], a, bv[2], bv[3]);
            }
        }
        __syncthreads();   // readers done before next issue overwrites
    }

    // rowsum reduce within quad
    rs0 += __shfl_xor_sync(0xFFFFFFFF, rs0, 1);
    rs0 += __shfl_xor_sync(0xFFFFFFFF, rs0, 2);
    rs1 += __shfl_xor_sync(0xFFFFFFFF, rs1, 1);
    rs1 += __shfl_xor_sync(0xFFFFFFFF, rs1, 2);
    const float inv0 = 1.0f / rs0;
    const float inv1 = 1.0f / rs1;

    // write: g_mid = tokens + O/lsum
    const int qg0 = q0 + w * 16 + grp;
#pragma unroll
    for (int dt = 0; dt < 8; dt++) {
        int d = dt * 8 + tg * 2;
        size_t i00 = ((size_t)n * CT + h * 64 + d) * LL + qg0;
        size_t i01 = i00 + LL;
        g_mid[i00]     = tokens[i00]     + o[dt][0] * inv0;
        g_mid[i01]     = tokens[i01]     + o[dt][1] * inv0;
        g_mid[i00 + 8] = tokens[i00 + 8] + o[dt][2] * inv1;
        g_mid[i01 + 8] = tokens[i01 + 8] + o[dt][3] * inv1;
    }
}

// ---------------------------------------------------------------------------
extern "C" void kernel_launch(void* const* d_in, const int* in_sizes, int n_in,
                              void* d_out, int out_size)
{
    (void)in_sizes; (void)n_in; (void)out_size;
    const float* tokens = (const float*)d_in[0];
    const float* kw = (const float*)d_in[1];
    const float* kb = (const float*)d_in[2];
    const float* kg = (const float*)d_in[3];
    const float* kbe = (const float*)d_in[4];
    const float* km = (const float*)d_in[5];
    const float* kvv = (const float*)d_in[6];
    const float* qw = (const float*)d_in[7];
    const float* qb = (const float*)d_in[8];
    const float* qg = (const float*)d_in[9];
    const float* qbe = (const float*)d_in[10];
    const float* qm = (const float*)d_in[11];
    const float* qvv = (const float*)d_in[12];
    const float* vw = (const float*)d_in[13];
    const float* vb = (const float*)d_in[14];
    const float* vg = (const float*)d_in[15];
    const float* vbe = (const float*)d_in[16];
    const float* vm = (const float*)d_in[17];
    const float* vvv = (const float*)d_in[18];
    const float* fw = (const float*)d_in[19];
    const float* fb = (const float*)d_in[20];
    const float* fg = (const float*)d_in[21];
    const float* fbe = (const float*)d_in[22];
    const float* fm = (const float*)d_in[23];
    const float* fvv = (const float*)d_in[24];

    const int smem64  = (2 * 64 * 36 + 2 * 32 * 136) * 4;    // 53248 B
    const int smem128 = (2 * 128 * 36 + 2 * 32 * 136) * 4;   // 71680 B
    cudaFuncSetAttribute(conv_mma_kernel<64>,
                         cudaFuncAttributeMaxDynamicSharedMemorySize, smem64);
    cudaFuncSetAttribute(conv_mma_kernel<128>,
                         cudaFuncAttributeMaxDynamicSharedMemorySize, smem128);
    cudaFuncSetAttribute(attn_mma_kernel,
                         cudaFuncAttributeMaxDynamicSharedMemorySize, SM_ATT_TOTAL);

    // K, Q convs: cout=512, groups=8 -> transposed bf16 [n][h][l][32]
    conv_mma_kernel<64><<<dim3(8, 8, 8), 256, smem64>>>(
        tokens, kw, kb, kg, kbe, km, kvv, nullptr, 0, OUT_KT, 0, 128, 64, 512);
    conv_mma_kernel<64><<<dim3(8, 8, 8), 256, smem64>>>(
        tokens, qw, qb, qg, qbe, qm, qvv, nullptr, 0, OUT_QT, 0, 128, 64, 512);
    // V conv: cout=1024, groups=8 -> bf16 [n][c][l]
    conv_mma_kernel<128><<<dim3(8, 8, 8), 256, smem128>>>(
        tokens, vw, vb, vg, vbe, vm, vvv, nullptr, 0, OUT_VB, 0, 128, 128, 1024);

    // Attention + residual -> g_mid
    attn_mma_kernel<<<dim3(8, HEADS, 8), 256, SM_ATT_TOTAL>>>(tokens);

    // FF conv (groups=1, tf32) + residual: g_mid -> d_out
    conv_mma_kernel<128><<<dim3(8, 8, 8), 256, smem128>>>(
        nullptr, fw, fb, fg, fbe, fm, fvv, (float*)d_out, 1, OUT_F32, 1,
        1024, 1024, 1024);
}